// round 4
// baseline (speedup 1.0000x reference)
#include <cuda_runtime.h>

// Problem constants
#define NPT   4096      // B*H*W = 4*32*32 output points
#define NOC   64        // output channels
#define NFEAT 576       // IC*K*K unfolded features
#define NGRP  144       // 4-feature groups
#define NCH   5         // subarray chunks (29,29,29,29,28 groups)

// Scratch (no allocations allowed -> device globals)
__device__ float    g_maxabs;
__device__ uint4    g_sv2[NGRP * NPT];             // [g][pt] -> stream words s0..s3
__device__ unsigned g_wpk[NCH * 8 * NOC * 32];     // [ch][tpn][oc][kw] s8x4, pads zeroed

// ---------------------------------------------------------------- max |w|
__global__ void k_maxabs(const float* __restrict__ w, int n) {
    __shared__ float red[32];
    float m = 0.f;
    for (int i = threadIdx.x; i < n; i += blockDim.x)
        m = fmaxf(m, fabsf(w[i]));
    for (int o = 16; o; o >>= 1) m = fmaxf(m, __shfl_xor_sync(0xffffffffu, m, o));
    if ((threadIdx.x & 31) == 0) red[threadIdx.x >> 5] = m;
    __syncthreads();
    if (threadIdx.x < 32) {
        int nw = (blockDim.x + 31) >> 5;
        m = (threadIdx.x < nw) ? red[threadIdx.x] : 0.f;
        for (int o = 16; o; o >>= 1) m = fmaxf(m, __shfl_xor_sync(0xffffffffu, m, o));
        if (threadIdx.x == 0) g_maxabs = (m > 0.f) ? m : 1.f;
    }
}

// ------------------- weight bit-slicing, packed per chunk with zero pads
__global__ void k_weights(const float* __restrict__ w) {
    int idx = blockIdx.x * blockDim.x + threadIdx.x;   // NOC * NCH * 32
    if (idx >= NOC * NCH * 32) return;
    int kw = idx & 31;
    int ch = (idx >> 5) % NCH;
    int o  = idx / (NCH * 32);
    int ng = (ch == 4) ? 28 : 29;
    unsigned pw[4] = {0,0,0,0}, nw[4] = {0,0,0,0};
    if (kw < ng) {
        float ma = g_maxabs;
        int g = ch * 29 + kw;
#pragma unroll
        for (int j = 0; j < 4; j++) {
            int f = 4 * g + j;
            float r  = w[o * NFEAT + f];
            float wp = fmaxf(r, 0.f);
            float wn = fmaxf(-r, 0.f);
            int pi = (int)rintf(__fdiv_rn(wp, ma) * 255.f);
            int ni = (int)rintf(__fdiv_rn(wn, ma) * 255.f);
#pragma unroll
            for (int t = 0; t < 4; t++) {
                pw[t] |= (unsigned)((pi >> (2 * t)) & 3) << (8 * j);
                nw[t] |= (unsigned)((ni >> (2 * t)) & 3) << (8 * j);
            }
        }
    }
#pragma unroll
    for (int t = 0; t < 4; t++) {
        g_wpk[((ch * 8 + t) * NOC + o) * 32 + kw]     = pw[t];
        g_wpk[((ch * 8 + 4 + t) * NOC + o) * 32 + kw] = nw[t];
    }
}

// -------------- input quantize + unfold + bit-stream pack ([g][pt] uint4)
__global__ void k_streams(const float* __restrict__ x) {
    int id = blockIdx.x * blockDim.x + threadIdx.x;   // NPT*NGRP
    if (id >= NPT * NGRP) return;
    int pt = id & (NPT - 1);
    int g  = id >> 12;
    int b = pt >> 10, p = pt & 1023, h = p >> 5, wc = p & 31;
    unsigned sw0 = 0, sw1 = 0, sw2 = 0, sw3 = 0;
#pragma unroll
    for (int j = 0; j < 4; j++) {
        int f = 4 * g + j;
        int c = f / 9, rem = f - 9 * c, kh = rem / 3, kw = rem - 3 * (rem / 3);
        int y = h + kh - 1, xx = wc + kw - 1;
        float v = 0.f;
        if ((unsigned)y < 32u && (unsigned)xx < 32u)
            v = x[((b * 64 + c) * 32 + y) * 32 + xx];
        v = fminf(fmaxf(v, -8.f), 7.9375f);
        int q = ((int)rintf(v * 16.f)) & 255;
        sw0 |= (unsigned)( q        & 3) << (8 * j);
        sw1 |= (unsigned)((q >> 2)  & 3) << (8 * j);
        sw2 |= (unsigned)((q >> 4)  & 3) << (8 * j);
        sw3 |= (unsigned)((q >> 6)  & 3) << (8 * j);
    }
    g_sv2[g * NPT + pt] = make_uint4(sw0, sw1, sw2, sw3);
}

// ---------------------------------------------------------- tensor MMA core
// Block: 256 thr = 8 warps. Tile: 32 pts x 32 oc. Warp: 16 pts x 8 oc, all
// (s,t,pn) accumulators; ADC clamp per chunk; chunks looped inside.
__device__ __forceinline__ void mma_s8(int d[4], unsigned a0, unsigned a1,
                                       unsigned a2, unsigned a3,
                                       unsigned b0, unsigned b1) {
    asm volatile(
        "mma.sync.aligned.m16n8k32.row.col.s32.s8.s8.s32 "
        "{%0,%1,%2,%3}, {%4,%5,%6,%7}, {%8,%9}, {%0,%1,%2,%3};"
        : "+r"(d[0]), "+r"(d[1]), "+r"(d[2]), "+r"(d[3])
        : "r"(a0), "r"(a1), "r"(a2), "r"(a3), "r"(b0), "r"(b1));
}

__global__ __launch_bounds__(256) void k_mma(float* __restrict__ out) {
    __shared__ unsigned a_sm[4][32][36];   // [s][pt][kw pad36] 18.4 KB
    __shared__ unsigned b_sm[8][32][36];   // [tpn][oc][kw pad36] 36.9 KB
    const int tid  = threadIdx.x;
    const int warp = tid >> 5, lane = tid & 31;
    const int gid  = lane >> 2, tig = lane & 3;
    const int ocg  = warp >> 1;
    const int m0   = (warp & 1) * 16;
    const int ptbase = blockIdx.x * 32;
    const int ocbase = blockIdx.y * 32;

    int diffd[4] = {0, 0, 0, 0};

    for (int c = 0; c < NCH; c++) {
        const int ng = (c == 4) ? 28 : 29;
        __syncthreads();
        // stage A: 32 pts x 32 kwords (zero pad)
        for (int i = tid; i < 32 * 32; i += 256) {
            int pt = i >> 5, kw = i & 31;
            uint4 v = make_uint4(0, 0, 0, 0);
            if (kw < ng) v = g_sv2[(c * 29 + kw) * NPT + ptbase + pt];
            a_sm[0][pt][kw] = v.x; a_sm[1][pt][kw] = v.y;
            a_sm[2][pt][kw] = v.z; a_sm[3][pt][kw] = v.w;
        }
        // stage B: 8 tpn x 32 oc x 32 kw (pads already zero in g_wpk)
        for (int j = tid; j < 8 * 32 * 8; j += 256) {
            int tpn = j >> 8, rest = j & 255;
            int oc = rest >> 3, kw4 = (rest & 7) * 4;
            uint4 v = *(const uint4*)&g_wpk[((c * 8 + tpn) * NOC + ocbase + oc) * 32 + kw4];
            b_sm[tpn][oc][kw4]     = v.x; b_sm[tpn][oc][kw4 + 1] = v.y;
            b_sm[tpn][oc][kw4 + 2] = v.z; b_sm[tpn][oc][kw4 + 3] = v.w;
        }
        __syncthreads();

#pragma unroll
        for (int pn = 0; pn < 2; pn++) {
            int acc[16][4];
#pragma unroll
            for (int i = 0; i < 16; i++)
#pragma unroll
                for (int e = 0; e < 4; e++) acc[i][e] = 0;

#pragma unroll
            for (int kb = 0; kb < 4; kb++) {
                unsigned a[4][4];
#pragma unroll
                for (int s = 0; s < 4; s++) {
                    a[s][0] = a_sm[s][m0 + gid    ][kb * 8 + tig];
                    a[s][1] = a_sm[s][m0 + gid + 8][kb * 8 + tig];
                    a[s][2] = a_sm[s][m0 + gid    ][kb * 8 + 4 + tig];
                    a[s][3] = a_sm[s][m0 + gid + 8][kb * 8 + 4 + tig];
                }
#pragma unroll
                for (int t = 0; t < 4; t++) {
                    unsigned b0 = b_sm[pn * 4 + t][ocg * 8 + gid][kb * 8 + tig];
                    unsigned b1 = b_sm[pn * 4 + t][ocg * 8 + gid][kb * 8 + 4 + tig];
#pragma unroll
                    for (int s = 0; s < 4; s++)
                        mma_s8(acc[s * 4 + t], a[s][0], a[s][1], a[s][2], a[s][3], b0, b1);
                }
            }
            // ADC clamp (ints >= 0, round = identity) + 4^(s+t) combine
#pragma unroll
            for (int s = 0; s < 4; s++)
#pragma unroll
                for (int t = 0; t < 4; t++) {
                    int sh = 2 * (s + t);
#pragma unroll
                    for (int e = 0; e < 4; e++) {
                        int v = min(acc[s * 4 + t][e], 31) << sh;
                        diffd[e] += pn ? -v : v;
                    }
                }
        }
    }

    const float scale = g_maxabs * (1.0f / 255.0f);
    const int oc0 = ocbase + ocg * 8 + tig * 2;
#pragma unroll
    for (int e = 0; e < 4; e++) {
        int pt = ptbase + m0 + gid + ((e & 2) ? 8 : 0);
        int oc = oc0 + (e & 1);
        int b = pt >> 10, p = pt & 1023;
        out[((b * NOC + oc) << 10) + p] = (float)diffd[e] * scale;
    }
}

// zero any tail elements of d_out beyond the conv output
__global__ void k_tail(float* __restrict__ out, int start, int total) {
    int i = start + blockIdx.x * blockDim.x + threadIdx.x;
    if (i < total) out[i] = 0.f;
}

extern "C" void kernel_launch(void* const* d_in, const int* in_sizes, int n_in,
                              void* d_out, int out_size) {
    const float* x = (const float*)d_in[0];   // inputs (4,64,32,32)
    const float* w = (const float*)d_in[1];   // weight (64,64,3,3)
    float* out = (float*)d_out;

    k_maxabs <<<1, 1024>>>(w, in_sizes[1]);
    k_weights<<<(NOC * NCH * 32 + 255) / 256, 256>>>(w);
    k_streams<<<(NPT * NGRP + 255) / 256, 256>>>(x);
    k_mma    <<<dim3(NPT / 32, NOC / 32), 256>>>(out);

    if (out_size > NPT * NOC) {
        int extra = out_size - NPT * NOC;
        k_tail<<<(extra + 255) / 256, 256>>>(out, NPT * NOC, out_size);
    }
}

// round 6
// speedup vs baseline: 1.0192x; 1.0192x over previous
#include <cuda_runtime.h>

// Problem constants
#define NPT   4096      // B*H*W = 4*32*32 output points
#define NOC   64        // output channels
#define NFEAT 576       // IC*K*K unfolded features
#define NGRP  144       // 4-feature groups
#define NCH   5         // subarray chunks (29,29,29,29,28 groups)
#define OBLK  8         // output channels per block
#define PTB   128       // points per block (threads)

// Scratch (no allocations allowed -> device globals)
__device__ float    g_maxabs;
__device__ unsigned g_wpos[NOC * NFEAT];        // [o][t][g]
__device__ unsigned g_wneg[NOC * NFEAT];
__device__ uint4    g_sv2[NGRP * NPT];          // [g][pt] -> stream words s0..s3
__device__ int      g_part[NCH * NOC * NPT];    // per-chunk partial diffs

// ---------------------------------------------------------------- max |w|
__global__ void k_maxabs(const float* __restrict__ w, int n) {
    __shared__ float red[32];
    float m = 0.f;
    for (int i = threadIdx.x; i < n; i += blockDim.x)
        m = fmaxf(m, fabsf(w[i]));
    for (int o = 16; o; o >>= 1) m = fmaxf(m, __shfl_xor_sync(0xffffffffu, m, o));
    if ((threadIdx.x & 31) == 0) red[threadIdx.x >> 5] = m;
    __syncthreads();
    if (threadIdx.x < 32) {
        int nw = (blockDim.x + 31) >> 5;
        m = (threadIdx.x < nw) ? red[threadIdx.x] : 0.f;
        for (int o = 16; o; o >>= 1) m = fmaxf(m, __shfl_xor_sync(0xffffffffu, m, o));
        if (threadIdx.x == 0) g_maxabs = (m > 0.f) ? m : 1.f;
    }
}

// ------------------------------------------- weight bit-slicing + packing
__global__ void k_weights(const float* __restrict__ w) {
    int idx = blockIdx.x * blockDim.x + threadIdx.x;
    if (idx >= NOC * NGRP) return;
    int o = idx / NGRP, g = idx % NGRP;
    float ma = g_maxabs;
    unsigned pw[4] = {0,0,0,0}, nw[4] = {0,0,0,0};
#pragma unroll
    for (int j = 0; j < 4; j++) {
        float r  = w[o * NFEAT + 4 * g + j];
        float wp = fmaxf(r, 0.f);
        float wn = fmaxf(-r, 0.f);
        int pi = (int)rintf(__fdiv_rn(wp, ma) * 255.f);
        int ni = (int)rintf(__fdiv_rn(wn, ma) * 255.f);
#pragma unroll
        for (int t = 0; t < 4; t++) {
            pw[t] |= (unsigned)((pi >> (2 * t)) & 3) << (8 * j);
            nw[t] |= (unsigned)((ni >> (2 * t)) & 3) << (8 * j);
        }
    }
#pragma unroll
    for (int t = 0; t < 4; t++) {
        g_wpos[o * NFEAT + t * NGRP + g] = pw[t];
        g_wneg[o * NFEAT + t * NGRP + g] = nw[t];
    }
}

// -------------- input quantize + unfold + bit-stream pack ([g][pt] uint4)
__global__ void k_streams(const float* __restrict__ x) {
    int id = blockIdx.x * blockDim.x + threadIdx.x;   // NPT*NGRP
    if (id >= NPT * NGRP) return;
    int pt = id & (NPT - 1);
    int g  = id >> 12;
    int b = pt >> 10, p = pt & 1023, h = p >> 5, wc = p & 31;
    unsigned sw0 = 0, sw1 = 0, sw2 = 0, sw3 = 0;
#pragma unroll
    for (int j = 0; j < 4; j++) {
        int f = 4 * g + j;
        int c = f / 9, rem = f - 9 * c, kh = rem / 3, kw = rem - 3 * (rem / 3);
        int y = h + kh - 1, xx = wc + kw - 1;
        float v = 0.f;
        if ((unsigned)y < 32u && (unsigned)xx < 32u)
            v = x[((b * 64 + c) * 32 + y) * 32 + xx];
        v = fminf(fmaxf(v, -8.f), 7.9375f);
        int q = ((int)rintf(v * 16.f)) & 255;
        sw0 |= (unsigned)( q        & 3) << (8 * j);
        sw1 |= (unsigned)((q >> 2)  & 3) << (8 * j);
        sw2 |= (unsigned)((q >> 4)  & 3) << (8 * j);
        sw3 |= (unsigned)((q >> 6)  & 3) << (8 * j);
    }
    g_sv2[g * NPT + pt] = make_uint4(sw0, sw1, sw2, sw3);
}

// ---------------------------------------------------------- main dp4a MAC
// grid: (NPT/PTB, NOC/OBLK, NCH). Block: 128 pts x 8 oc x 1 chunk.
// A-tile (29 grp x 128 pt x 16B = 58KB) staged to smem; inner loop LDS-only,
// software-pipelined 1 group ahead; chunk padded to 29 groups with zeros.
__global__ __launch_bounds__(PTB) void k_main() {
    __shared__ uint4    s_a[30][PTB];        // [gl][pt], row 29 zero pad
    __shared__ unsigned s_w[OBLK][30][8];    // [ol][gl][pos t0..3 | neg t0..3]
    const int tid   = threadIdx.x;
    const int ptb   = blockIdx.x * PTB;
    const int obase = blockIdx.y * OBLK;
    const int c     = blockIdx.z;
    const int g0    = c * 29;
    const int ng    = (c == 4) ? 28 : 29;

    // stage A-tile: coalesced (consecutive pt per lane), zero pads
    for (int i = tid; i < 30 * PTB; i += PTB) {
        int gl = i >> 7, pt = i & (PTB - 1);
        uint4 v = make_uint4(0, 0, 0, 0);
        if (gl < ng) v = g_sv2[(g0 + gl) * NPT + ptb + pt];
        s_a[gl][pt] = v;
    }
    // stage weights (zero pads)
    for (int i = tid; i < OBLK * 30 * 8; i += PTB) {
        int r = i & 7, rest = i >> 3;
        int gl = rest % 30, ol = rest / 30;
        unsigned v = 0;
        if (gl < ng) {
            const unsigned* src = (r < 4) ? g_wpos : g_wneg;
            v = src[(obase + ol) * NFEAT + (r & 3) * NGRP + g0 + gl];
        }
        s_w[ol][gl][r] = v;
    }
    __syncthreads();

#pragma unroll 1
    for (int ol = 0; ol < OBLK; ol++) {
        int accp[16], accn[16];
#pragma unroll
        for (int i = 0; i < 16; i++) { accp[i] = 0; accn[i] = 0; }

        // software pipeline: operands for gl=0 preloaded
        uint4 a  = s_a[0][tid];
        uint4 wp = *reinterpret_cast<const uint4*>(&s_w[ol][0][0]);
        uint4 wn = *reinterpret_cast<const uint4*>(&s_w[ol][0][4]);

#pragma unroll 1
        for (int gl = 0; gl < 29; gl++) {
            // prefetch next group (row 29 is zero pad; always safe)
            uint4 a_n  = s_a[gl + 1][tid];
            uint4 wp_n = *reinterpret_cast<const uint4*>(&s_w[ol][gl + 1][0]);
            uint4 wn_n = *reinterpret_cast<const uint4*>(&s_w[ol][gl + 1][4]);

            const unsigned av[4] = {a.x, a.y, a.z, a.w};
            const unsigned pv[4] = {wp.x, wp.y, wp.z, wp.w};
            const unsigned nv[4] = {wn.x, wn.y, wn.z, wn.w};
#pragma unroll
            for (int s = 0; s < 4; s++)
#pragma unroll
                for (int t = 0; t < 4; t++) {
                    accp[s * 4 + t] = __dp4a((int)av[s], (int)pv[t], accp[s * 4 + t]);
                    accn[s * 4 + t] = __dp4a((int)av[s], (int)nv[t], accn[s * 4 + t]);
                }
            a = a_n; wp = wp_n; wn = wn_n;
        }

        int diff = 0;
#pragma unroll
        for (int s = 0; s < 4; s++)
#pragma unroll
            for (int t = 0; t < 4; t++)
                diff += (min(accp[s * 4 + t], 31) - min(accn[s * 4 + t], 31))
                        << (2 * (s + t));
        g_part[((c * NOC + obase + ol) << 12) + ptb + tid] = diff;
    }
}

// -------------------------------------------- combine partials + scale
__global__ void k_final(float* __restrict__ out) {
    int id = blockIdx.x * blockDim.x + threadIdx.x;   // NOC*NPT
    if (id >= NOC * NPT) return;
    int oc = id >> 12, pt = id & (NPT - 1);
    int b = pt >> 10, p = pt & 1023;
    int d = 0;
#pragma unroll
    for (int c = 0; c < NCH; c++)
        d += g_part[((c * NOC + oc) << 12) + pt];
    out[((b * NOC + oc) << 10) + p] = (float)d * (g_maxabs * (1.0f / 255.0f));
}

// zero any tail elements of d_out beyond the conv output
__global__ void k_tail(float* __restrict__ out, int start, int total) {
    int i = start + blockIdx.x * blockDim.x + threadIdx.x;
    if (i < total) out[i] = 0.f;
}

extern "C" void kernel_launch(void* const* d_in, const int* in_sizes, int n_in,
                              void* d_out, int out_size) {
    const float* x = (const float*)d_in[0];   // inputs (4,64,32,32)
    const float* w = (const float*)d_in[1];   // weight (64,64,3,3)
    float* out = (float*)d_out;

    k_maxabs <<<1, 1024>>>(w, in_sizes[1]);
    k_weights<<<(NOC * NGRP + 255) / 256, 256>>>(w);
    k_streams<<<(NPT * NGRP + 255) / 256, 256>>>(x);
    k_main   <<<dim3(NPT / PTB, NOC / OBLK, NCH), PTB>>>();
    k_final  <<<(NOC * NPT + 255) / 256, 256>>>(out);

    if (out_size > NPT * NOC) {
        int extra = out_size - NPT * NOC;
        k_tail<<<(extra + 255) / 256, 256>>>(out, NPT * NOC, out_size);
    }
}

// round 7
// speedup vs baseline: 1.3175x; 1.2927x over previous
#include <cuda_runtime.h>

// Problem constants
#define NPT   4096      // B*H*W = 4*32*32 output points
#define NOC   64        // output channels
#define NFEAT 576       // IC*K*K unfolded features
#define NGRP  144       // 4-feature groups
#define NCH   5         // subarray chunks (29,29,29,29,28 groups)
#define PM    2048      // points handled by the MMA role; rest by dp4a role
#define MMA_BLOCKS 256  // (PM/16) * (NOC/32)
#define DP_OBLK 4
#define DP_BLOCKS (((NPT - PM) / 128) * (NOC / DP_OBLK) * NCH)   // 16*16*5 = 1280

// Scratch (no allocations allowed -> device globals)
__device__ float    g_maxabs;
__device__ unsigned g_wpos[NOC * NFEAT];        // [o][t][g] packed bytes (dp4a B)
__device__ unsigned g_wneg[NOC * NFEAT];
__device__ unsigned g_wpk[NCH * 8 * NOC * 32];  // [ch][tpn][oc][kw] (mma B), pads 0
__device__ uint4    g_sv2[NGRP * NPT];          // [g][pt] stream words s0..s3
__device__ int      g_part[NCH * NOC * NPT];    // per-chunk partials (dp4a half)

// ---------------------------------------------------------------- max |w|
__global__ void k_maxabs(const float* __restrict__ w, int n) {
    __shared__ float red[32];
    float m = 0.f;
    for (int i = threadIdx.x; i < n; i += blockDim.x)
        m = fmaxf(m, fabsf(w[i]));
    for (int o = 16; o; o >>= 1) m = fmaxf(m, __shfl_xor_sync(0xffffffffu, m, o));
    if ((threadIdx.x & 31) == 0) red[threadIdx.x >> 5] = m;
    __syncthreads();
    if (threadIdx.x < 32) {
        int nw = (blockDim.x + 31) >> 5;
        m = (threadIdx.x < nw) ? red[threadIdx.x] : 0.f;
        for (int o = 16; o; o >>= 1) m = fmaxf(m, __shfl_xor_sync(0xffffffffu, m, o));
        if (threadIdx.x == 0) g_maxabs = (m > 0.f) ? m : 1.f;
    }
}

// ---------------- weight bit-slicing: both dp4a and mma layouts
__global__ void k_weights(const float* __restrict__ w) {
    int idx = blockIdx.x * blockDim.x + threadIdx.x;   // NOC * NCH * 32
    if (idx >= NOC * NCH * 32) return;
    int kw = idx & 31;
    int ch = (idx >> 5) % NCH;
    int o  = idx / (NCH * 32);
    int ng = (ch == 4) ? 28 : 29;
    unsigned pw[4] = {0,0,0,0}, nw[4] = {0,0,0,0};
    if (kw < ng) {
        float ma = g_maxabs;
        int g = ch * 29 + kw;
#pragma unroll
        for (int j = 0; j < 4; j++) {
            float r  = w[o * NFEAT + 4 * g + j];
            float wp = fmaxf(r, 0.f);
            float wn = fmaxf(-r, 0.f);
            int pi = (int)rintf(__fdiv_rn(wp, ma) * 255.f);
            int ni = (int)rintf(__fdiv_rn(wn, ma) * 255.f);
#pragma unroll
            for (int t = 0; t < 4; t++) {
                pw[t] |= (unsigned)((pi >> (2 * t)) & 3) << (8 * j);
                nw[t] |= (unsigned)((ni >> (2 * t)) & 3) << (8 * j);
            }
        }
    }
#pragma unroll
    for (int t = 0; t < 4; t++) {
        g_wpk[((ch * 8 + t) * NOC + o) * 32 + kw]     = pw[t];
        g_wpk[((ch * 8 + 4 + t) * NOC + o) * 32 + kw] = nw[t];
    }
    if (kw < ng) {
        int g = ch * 29 + kw;
#pragma unroll
        for (int t = 0; t < 4; t++) {
            g_wpos[o * NFEAT + t * NGRP + g] = pw[t];
            g_wneg[o * NFEAT + t * NGRP + g] = nw[t];
        }
    }
}

// -------------- input quantize + unfold + bit-stream pack ([g][pt] uint4)
__global__ void k_streams(const float* __restrict__ x) {
    int id = blockIdx.x * blockDim.x + threadIdx.x;   // NPT*NGRP
    if (id >= NPT * NGRP) return;
    int pt = id & (NPT - 1);
    int g  = id >> 12;
    int b = pt >> 10, p = pt & 1023, h = p >> 5, wc = p & 31;
    unsigned sw0 = 0, sw1 = 0, sw2 = 0, sw3 = 0;
#pragma unroll
    for (int j = 0; j < 4; j++) {
        int f = 4 * g + j;
        int c = f / 9, rem = f - 9 * c, kh = rem / 3, kw = rem - 3 * (rem / 3);
        int y = h + kh - 1, xx = wc + kw - 1;
        float v = 0.f;
        if ((unsigned)y < 32u && (unsigned)xx < 32u)
            v = x[((b * 64 + c) * 32 + y) * 32 + xx];
        v = fminf(fmaxf(v, -8.f), 7.9375f);
        int q = ((int)rintf(v * 16.f)) & 255;
        sw0 |= (unsigned)( q        & 3) << (8 * j);
        sw1 |= (unsigned)((q >> 2)  & 3) << (8 * j);
        sw2 |= (unsigned)((q >> 4)  & 3) << (8 * j);
        sw3 |= (unsigned)((q >> 6)  & 3) << (8 * j);
    }
    g_sv2[g * NPT + pt] = make_uint4(sw0, sw1, sw2, sw3);
}

// ---------------------------------------------------------------- mma op
__device__ __forceinline__ void mma_s8(int d[4], unsigned a0, unsigned a1,
                                       unsigned a2, unsigned a3,
                                       unsigned b0, unsigned b1) {
    asm volatile(
        "mma.sync.aligned.m16n8k32.row.col.s32.s8.s8.s32 "
        "{%0,%1,%2,%3}, {%4,%5,%6,%7}, {%8,%9}, {%0,%1,%2,%3};"
        : "+r"(d[0]), "+r"(d[1]), "+r"(d[2]), "+r"(d[3])
        : "r"(a0), "r"(a1), "r"(a2), "r"(a3), "r"(b0), "r"(b1));
}

// =========================== hybrid main kernel ===========================
// 128 threads. Blocks [0, MMA_BLOCKS): tensor-pipe IMMA role, pts [0, PM).
// Blocks [MMA_BLOCKS, +DP_BLOCKS): fma-pipe dp4a role, pts [PM, NPT).
__global__ __launch_bounds__(128, 4) void k_hybrid(float* __restrict__ out) {
    __shared__ union {
        struct { unsigned a[4][16][36]; unsigned b[8][32][36]; } m;  // 45KB
        struct { unsigned w[DP_OBLK][29][8]; } d;                    // 3.6KB
    } sm;
    const int tid = threadIdx.x;

    if (blockIdx.x < MMA_BLOCKS) {
        // ---------------- MMA role: tile 16 pts x 32 oc, all chunks ----------------
        const int warp = tid >> 5, lane = tid & 31;
        const int gid  = lane >> 2, tig = lane & 3;
        const int ptbase = (blockIdx.x >> 1) << 4;
        const int ocbase = (blockIdx.x & 1) << 5;

        int diffd[4] = {0, 0, 0, 0};

        for (int c = 0; c < NCH; c++) {
            const int ng = (c == 4) ? 28 : 29;
            __syncthreads();
            for (int i = tid; i < 16 * 32; i += 128) {
                int pt = i >> 5, kw = i & 31;
                uint4 v = make_uint4(0, 0, 0, 0);
                if (kw < ng) v = g_sv2[(c * 29 + kw) * NPT + ptbase + pt];
                sm.m.a[0][pt][kw] = v.x; sm.m.a[1][pt][kw] = v.y;
                sm.m.a[2][pt][kw] = v.z; sm.m.a[3][pt][kw] = v.w;
            }
            for (int j = tid; j < 8 * 32 * 8; j += 128) {
                int tpn = j >> 8, rest = j & 255;
                int oc = rest >> 3, kw4 = (rest & 7) * 4;
                uint4 v = *(const uint4*)&g_wpk[((c * 8 + tpn) * NOC + ocbase + oc) * 32 + kw4];
                sm.m.b[tpn][oc][kw4]     = v.x; sm.m.b[tpn][oc][kw4 + 1] = v.y;
                sm.m.b[tpn][oc][kw4 + 2] = v.z; sm.m.b[tpn][oc][kw4 + 3] = v.w;
            }
            __syncthreads();

#pragma unroll
            for (int pn = 0; pn < 2; pn++) {
                int acc[16][4];
#pragma unroll
                for (int i = 0; i < 16; i++)
#pragma unroll
                    for (int e = 0; e < 4; e++) acc[i][e] = 0;

#pragma unroll
                for (int kb = 0; kb < 4; kb++) {
                    unsigned a[4][4];
#pragma unroll
                    for (int s = 0; s < 4; s++) {
                        a[s][0] = sm.m.a[s][gid    ][kb * 8 + tig];
                        a[s][1] = sm.m.a[s][gid + 8][kb * 8 + tig];
                        a[s][2] = sm.m.a[s][gid    ][kb * 8 + 4 + tig];
                        a[s][3] = sm.m.a[s][gid + 8][kb * 8 + 4 + tig];
                    }
#pragma unroll
                    for (int t = 0; t < 4; t++) {
                        unsigned b0 = sm.m.b[pn * 4 + t][warp * 8 + gid][kb * 8 + tig];
                        unsigned b1 = sm.m.b[pn * 4 + t][warp * 8 + gid][kb * 8 + 4 + tig];
#pragma unroll
                        for (int s = 0; s < 4; s++)
                            mma_s8(acc[s * 4 + t], a[s][0], a[s][1], a[s][2], a[s][3], b0, b1);
                    }
                }
#pragma unroll
                for (int s = 0; s < 4; s++)
#pragma unroll
                    for (int t = 0; t < 4; t++) {
                        int sh = 2 * (s + t);
#pragma unroll
                        for (int e = 0; e < 4; e++) {
                            int v = min(acc[s * 4 + t][e], 31) << sh;
                            diffd[e] += pn ? -v : v;
                        }
                    }
            }
        }

        const float scale = g_maxabs * (1.0f / 255.0f);
        const int oc0 = ocbase + warp * 8 + tig * 2;
#pragma unroll
        for (int e = 0; e < 4; e++) {
            int pt = ptbase + gid + ((e & 2) ? 8 : 0);
            int oc = oc0 + (e & 1);
            int b = pt >> 10, p = pt & 1023;
            out[((b * NOC + oc) << 10) + p] = (float)diffd[e] * scale;
        }
    } else {
        // ---------------- dp4a role: 128 pts x 4 oc x 1 chunk ----------------
        const int bid   = blockIdx.x - MMA_BLOCKS;      // 0..1279
        const int c     = bid >> 8;                     // /256
        const int rest  = bid & 255;
        const int obase = (rest & 15) * DP_OBLK;
        const int ptb   = PM + (rest >> 4) * 128;
        const int g0    = c * 29;
        const int ng    = (c == 4) ? 28 : 29;
        const int pt    = ptb + tid;

        for (int i = tid; i < DP_OBLK * 29 * 8; i += 128) {
            int r = i & 7, rr = i >> 3;
            int gl = rr % 29, ol = rr / 29;
            unsigned v = 0;
            if (gl < ng) {
                const unsigned* src = (r < 4) ? g_wpos : g_wneg;
                v = src[(obase + ol) * NFEAT + (r & 3) * NGRP + g0 + gl];
            }
            sm.d.w[ol][gl][r] = v;
        }
        __syncthreads();

        const uint4* __restrict__ sv = g_sv2 + g0 * NPT + pt;

#pragma unroll 1
        for (int ol = 0; ol < DP_OBLK; ol++) {
            int accp[16], accn[16];
#pragma unroll
            for (int i = 0; i < 16; i++) { accp[i] = 0; accn[i] = 0; }
#pragma unroll 2
            for (int gl = 0; gl < ng; gl++) {
                uint4 a  = sv[gl * NPT];
                uint4 wp = *reinterpret_cast<const uint4*>(&sm.d.w[ol][gl][0]);
                uint4 wn = *reinterpret_cast<const uint4*>(&sm.d.w[ol][gl][4]);
                const unsigned av[4] = {a.x, a.y, a.z, a.w};
                const unsigned pv[4] = {wp.x, wp.y, wp.z, wp.w};
                const unsigned nv[4] = {wn.x, wn.y, wn.z, wn.w};
#pragma unroll
                for (int s = 0; s < 4; s++)
#pragma unroll
                    for (int t = 0; t < 4; t++) {
                        accp[s * 4 + t] = __dp4a((int)av[s], (int)pv[t], accp[s * 4 + t]);
                        accn[s * 4 + t] = __dp4a((int)av[s], (int)nv[t], accn[s * 4 + t]);
                    }
            }
            int diff = 0;
#pragma unroll
            for (int s = 0; s < 4; s++)
#pragma unroll
                for (int t = 0; t < 4; t++)
                    diff += (min(accp[s * 4 + t], 31) - min(accn[s * 4 + t], 31))
                            << (2 * (s + t));
            g_part[((c * NOC + obase + ol) << 12) + pt] = diff;
        }
    }
}

// -------------------- combine dp4a partials + scale (pts >= PM only)
__global__ void k_final(float* __restrict__ out) {
    int id = blockIdx.x * blockDim.x + threadIdx.x;   // NOC * (NPT-PM)
    if (id >= NOC * (NPT - PM)) return;
    int oc = id / (NPT - PM);
    int pt = PM + (id % (NPT - PM));
    int b = pt >> 10, p = pt & 1023;
    int d = 0;
#pragma unroll
    for (int c = 0; c < NCH; c++)
        d += g_part[((c * NOC + oc) << 12) + pt];
    out[((b * NOC + oc) << 10) + p] = (float)d * (g_maxabs * (1.0f / 255.0f));
}

// zero any tail elements of d_out beyond the conv output
__global__ void k_tail(float* __restrict__ out, int start, int total) {
    int i = start + blockIdx.x * blockDim.x + threadIdx.x;
    if (i < total) out[i] = 0.f;
}

extern "C" void kernel_launch(void* const* d_in, const int* in_sizes, int n_in,
                              void* d_out, int out_size) {
    const float* x = (const float*)d_in[0];   // inputs (4,64,32,32)
    const float* w = (const float*)d_in[1];   // weight (64,64,3,3)
    float* out = (float*)d_out;

    k_maxabs <<<1, 1024>>>(w, in_sizes[1]);
    k_weights<<<(NOC * NCH * 32 + 255) / 256, 256>>>(w);
    k_streams<<<(NPT * NGRP + 255) / 256, 256>>>(x);
    k_hybrid <<<MMA_BLOCKS + DP_BLOCKS, 128>>>(out);
    k_final  <<<(NOC * (NPT - PM) + 255) / 256, 256>>>(out);

    if (out_size > NPT * NOC) {
        int extra = out_size - NPT * NOC;
        k_tail<<<(extra + 255) / 256, 256>>>(out, NPT * NOC, out_size);
    }
}